// round 14
// baseline (speedup 1.0000x reference)
#include <cuda_runtime.h>
#include <cuda_bf16.h>

// Retrace loss — persistent CTAs (5/SM), scalar coalesced loads + warp-private
// smem transpose (the R10 dataflow), cross-row software pipeline.
// grid = 740 = 148 SM * 5 CTA (single wave); reg cap 51 via launch_bounds.
// Per row iteration:
//   1. build affine maps from regs loaded LAST iteration, STS to warp slice
//   2. issue next row's 25 loads (fly during this row's scan)
//   3. LDS float4, serial compose 4, one warp suffix scan
//   4. cross-warp combine: double-buffered totals, ONE __syncthreads,
//      redundant per-thread composition (no serial t0 section)
//   5. epilogue -> per-thread double accumulator
// Completion: one arrival per CTA; wrap-around counter -> deterministic replays.
// Affine composition: (A1,B1) o (A2,B2) = (A1 + B1*A2, B1*B2).

#define S_STRIDE 1025
#define T_LEN    1024
#define NROWS    4096
#define GAMMA_F  0.99f
#define EPS_F    1e-10f
#define NTHREADS 256
#define GRID     740

__device__ double   g_part[GRID];
__device__ unsigned g_cnt = 0;   // wraps at GRID-1 -> deterministic across replays

struct Aff { float a, b; };

__device__ __forceinline__ Aff comp(Aff f, Aff g) {
    Aff r;
    r.a = fmaf(f.b, g.a, f.a);
    r.b = f.b * g.b;
    return r;
}

struct RowRegs {
    float pt[4], pb[4], rv[4], ev[4], tq[4], qv[4];
    float init;
};

__device__ __forceinline__ void load_row(RowRegs& R, long base, int seg, int lane,
                                         const float* __restrict__ Q,
                                         const float* __restrict__ eQ,
                                         const float* __restrict__ tQ,
                                         const float* __restrict__ r,
                                         const float* __restrict__ tp,
                                         const float* __restrict__ bp)
{
#pragma unroll
    for (int p = 0; p < 4; p++) {
        const int i  = seg + p * 32 + lane;               // global col, 0..1023
        const int i2 = (i < T_LEN - 1) ? i + 2 : T_LEN;   // clamp; unused if i==1023
        R.pt[p] = __ldg(&tp[base + i2]);
        R.pb[p] = __ldg(&bp[base + i2]);
        R.rv[p] = __ldg(&r [base + i + 1]);
        R.ev[p] = __ldg(&eQ[base + i2]);
        R.tq[p] = __ldg(&tQ[base + i2]);
        R.qv[p] = __ldg(&Q [base + i]);
    }
    R.init = __ldg(&Q[base + T_LEN]);
}

__global__ void __launch_bounds__(NTHREADS, 5)
retrace_kernel(const float* __restrict__ Q,
               const float* __restrict__ eQ,
               const float* __restrict__ tQ,
               const float* __restrict__ r,
               const float* __restrict__ tp,
               const float* __restrict__ bp,
               float* __restrict__ out)
{
    __shared__ __align__(16) float sA [8][128];
    __shared__ __align__(16) float sB [8][128];
    __shared__ __align__(16) float sQv[8][128];
    __shared__ float swA[2][8], swB[2][8];   // double-buffered warp totals
    __shared__ double ssum[8];
    __shared__ bool s_last;

    const int bid = blockIdx.x;
    const int t = threadIdx.x;
    const int lane = t & 31;
    const int w = t >> 5;
    const int seg = w * 128;

    double acc = 0.0;       // per-thread squared-error accumulator across rows
    RowRegs R;

    int row = bid;
    load_row(R, (long)row * S_STRIDE, seg, lane, Q, eQ, tQ, r, tp, bp);

    int buf = 0;
    while (row < NROWS) {
        const int next = row + GRID;

        // ---- 1. build maps for current row from in-register loads, stage to smem
        float a_[4], b_[4], q_[4];
#pragma unroll
        for (int p = 0; p < 4; p++) {
            const int i = seg + p * 32 + lane;
            if (i < T_LEN - 1) {
                const float c = fminf(fmaxf(__fdividef(R.pt[p], R.pb[p]), EPS_F), 1.0f);
                b_[p] = GAMMA_F * c;
                a_[p] = fmaf(GAMMA_F, R.ev[p], R.rv[p]) - b_[p] * R.tq[p];
            } else {               // i == 1023: identity map
                a_[p] = 0.0f; b_[p] = 1.0f;
            }
            q_[p] = R.qv[p];
        }
        const float init = R.init;

        __syncwarp();              // prior iteration's LDS of this slice is done
#pragma unroll
        for (int p = 0; p < 4; p++) {
            const int il = p * 32 + lane;
            sA [w][il] = a_[p];
            sB [w][il] = b_[p];
            sQv[w][il] = q_[p];
        }
        __syncwarp();

        // ---- 2. issue next row's loads now; they fly during the scan below
        if (next < NROWS)
            load_row(R, (long)next * S_STRIDE, seg, lane, Q, eQ, tQ, r, tp, bp);

        // ---- 3. contiguous read-back: lane owns cols seg + 4*lane .. +3
        const float4 a4 = reinterpret_cast<const float4*>(sA [w])[lane];
        const float4 b4 = reinterpret_cast<const float4*>(sB [w])[lane];
        const float4 q4 = reinterpret_cast<const float4*>(sQv[w])[lane];
        Aff loc[4] = { {a4.x, b4.x}, {a4.y, b4.y}, {a4.z, b4.z}, {a4.w, b4.w} };
        const float qv[4] = { q4.x, q4.y, q4.z, q4.w };

        // serial suffix composition within thread
        Aff suf[4];
        suf[3] = loc[3];
#pragma unroll
        for (int k = 2; k >= 0; k--) suf[k] = comp(loc[k], suf[k + 1]);

        // single warp-level inclusive suffix scan of thread aggregates
        Aff v = suf[0];
#pragma unroll
        for (int off = 1; off < 32; off <<= 1) {
            const float oa = __shfl_down_sync(0xffffffffu, v.a, off);
            const float ob = __shfl_down_sync(0xffffffffu, v.b, off);
            if (lane + off < 32) { Aff g; g.a = oa; g.b = ob; v = comp(v, g); }
        }

        // in-warp EXCLUSIVE suffix (threads lane+1..31)
        const float ea = __shfl_down_sync(0xffffffffu, v.a, 1);
        const float eb = __shfl_down_sync(0xffffffffu, v.b, 1);
        Aff inwexcl;
        if (lane == 31) { inwexcl.a = 0.0f; inwexcl.b = 1.0f; }
        else            { inwexcl.a = ea;   inwexcl.b = eb;   }

        // ---- 4. cross-warp: publish totals (double-buffered), ONE barrier,
        //         then redundant per-thread composition of later warps
        if (lane == 0) { swA[buf][w] = v.a; swB[buf][w] = v.b; }
        __syncthreads();
        Aff W; W.a = 0.0f; W.b = 1.0f;
        for (int ww = 7; ww > w; ww--) {
            Aff tot; tot.a = swA[buf][ww]; tot.b = swB[buf][ww];
            W = comp(tot, W);
        }
        const Aff S = comp(inwexcl, W);

        // ---- 5. epilogue: apply composed maps, accumulate squared error
        float fsum = 0.0f;
#pragma unroll
        for (int k = 0; k < 4; k++) {
            const Aff m = comp(suf[k], S);
            const float y = fmaf(m.b, init, m.a);
            const float d = qv[k] - y;
            fsum = fmaf(d, d, fsum);
        }
        acc += (double)fsum;

        buf ^= 1;
        row = next;
    }

    // ---- final: block-reduce per-thread doubles, one arrival per CTA
#pragma unroll
    for (int off = 16; off > 0; off >>= 1)
        acc += __shfl_down_sync(0xffffffffu, acc, off);
    if (lane == 0) ssum[w] = acc;
    __syncthreads();

    if (t == 0) {
        double x = 0.0;
#pragma unroll
        for (int i = 0; i < 8; i++) x += ssum[i];
        __stcg(&g_part[bid], x);
        __threadfence();
        const unsigned old = atomicInc(&g_cnt, GRID - 1);  // wraps after GRID arrivals
        s_last = (old == GRID - 1);
    }
    __syncthreads();

    // ---- very last CTA reduces all partials and writes output
    if (s_last) {
        double x = 0.0;
        for (int i = t; i < GRID; i += NTHREADS)
            x += __ldcg(&g_part[i]);
#pragma unroll
        for (int off = 16; off > 0; off >>= 1)
            x += __shfl_down_sync(0xffffffffu, x, off);
        __shared__ double fs2[8];
        if (lane == 0) fs2[w] = x;
        __syncthreads();
        if (t == 0) {
            double tot = 0.0;
#pragma unroll
            for (int i = 0; i < 8; i++) tot += fs2[i];
            out[0] = (float)(tot / (double)((long long)NROWS * T_LEN));
        }
    }
}

extern "C" void kernel_launch(void* const* d_in, const int* in_sizes, int n_in,
                              void* d_out, int out_size)
{
    const float* Q   = (const float*)d_in[0];
    const float* eQ  = (const float*)d_in[1];
    const float* tQ  = (const float*)d_in[2];
    const float* r   = (const float*)d_in[3];
    const float* tp  = (const float*)d_in[4];
    const float* bp  = (const float*)d_in[5];
    float* out = (float*)d_out;

    retrace_kernel<<<GRID, NTHREADS>>>(Q, eQ, tQ, r, tp, bp, out);
}

// round 15
// speedup vs baseline: 1.1059x; 1.1059x over previous
#include <cuda_runtime.h>
#include <cuda_bf16.h>

// Retrace loss — persistent CTAs (4/SM, the proven R10 skeleton), scalar
// coalesced streaming loads + warp-private smem transpose, cross-row pipeline.
// grid = 592 = 148 SM * 4 CTA (single wave).
// Per row iteration:
//   1. build affine maps from regs loaded LAST iteration, STS to warp slice
//   2. issue next row's 25 loads (fly during this row's scan)
//   3. LDS float4, serial compose 4, one warp suffix scan
//   4. cross-warp combine: double-buffered totals, ONE __syncthreads,
//      redundant per-thread composition (no serial t0 section)
//   5. epilogue -> per-thread double accumulator
// All input loads use __ldcs (read-once data, evict-first streaming).
// Completion: one arrival per CTA; wrap-around counter -> deterministic replays.
// Affine composition: (A1,B1) o (A2,B2) = (A1 + B1*A2, B1*B2).

#define S_STRIDE 1025
#define T_LEN    1024
#define NROWS    4096
#define GAMMA_F  0.99f
#define EPS_F    1e-10f
#define NTHREADS 256
#define GRID     592

__device__ double   g_part[GRID];
__device__ unsigned g_cnt = 0;   // wraps at GRID-1 -> deterministic across replays

struct Aff { float a, b; };

__device__ __forceinline__ Aff comp(Aff f, Aff g) {
    Aff r;
    r.a = fmaf(f.b, g.a, f.a);
    r.b = f.b * g.b;
    return r;
}

struct RowRegs {
    float pt[4], pb[4], rv[4], ev[4], tq[4], qv[4];
    float init;
};

__device__ __forceinline__ void load_row(RowRegs& R, long base, int seg, int lane,
                                         const float* __restrict__ Q,
                                         const float* __restrict__ eQ,
                                         const float* __restrict__ tQ,
                                         const float* __restrict__ r,
                                         const float* __restrict__ tp,
                                         const float* __restrict__ bp)
{
#pragma unroll
    for (int p = 0; p < 4; p++) {
        const int i  = seg + p * 32 + lane;               // global col, 0..1023
        const int i2 = (i < T_LEN - 1) ? i + 2 : T_LEN;   // clamp; unused if i==1023
        R.pt[p] = __ldcs(&tp[base + i2]);
        R.pb[p] = __ldcs(&bp[base + i2]);
        R.rv[p] = __ldcs(&r [base + i + 1]);
        R.ev[p] = __ldcs(&eQ[base + i2]);
        R.tq[p] = __ldcs(&tQ[base + i2]);
        R.qv[p] = __ldcs(&Q [base + i]);
    }
    R.init = __ldcs(&Q[base + T_LEN]);
}

__global__ void __launch_bounds__(NTHREADS, 4)
retrace_kernel(const float* __restrict__ Q,
               const float* __restrict__ eQ,
               const float* __restrict__ tQ,
               const float* __restrict__ r,
               const float* __restrict__ tp,
               const float* __restrict__ bp,
               float* __restrict__ out)
{
    __shared__ __align__(16) float sA [8][128];
    __shared__ __align__(16) float sB [8][128];
    __shared__ __align__(16) float sQv[8][128];
    __shared__ float swA[2][8], swB[2][8];   // double-buffered warp totals
    __shared__ double ssum[8];
    __shared__ bool s_last;

    const int bid = blockIdx.x;
    const int t = threadIdx.x;
    const int lane = t & 31;
    const int w = t >> 5;
    const int seg = w * 128;

    double acc = 0.0;       // per-thread squared-error accumulator across rows
    RowRegs R;

    int row = bid;
    load_row(R, (long)row * S_STRIDE, seg, lane, Q, eQ, tQ, r, tp, bp);

    int buf = 0;
    while (row < NROWS) {
        const int next = row + GRID;

        // ---- 1. build maps for current row from in-register loads, stage to smem
        float a_[4], b_[4], q_[4];
#pragma unroll
        for (int p = 0; p < 4; p++) {
            const int i = seg + p * 32 + lane;
            if (i < T_LEN - 1) {
                const float c = fminf(fmaxf(__fdividef(R.pt[p], R.pb[p]), EPS_F), 1.0f);
                b_[p] = GAMMA_F * c;
                a_[p] = fmaf(GAMMA_F, R.ev[p], R.rv[p]) - b_[p] * R.tq[p];
            } else {               // i == 1023: identity map
                a_[p] = 0.0f; b_[p] = 1.0f;
            }
            q_[p] = R.qv[p];
        }
        const float init = R.init;

        __syncwarp();              // prior iteration's LDS of this slice is done
#pragma unroll
        for (int p = 0; p < 4; p++) {
            const int il = p * 32 + lane;
            sA [w][il] = a_[p];
            sB [w][il] = b_[p];
            sQv[w][il] = q_[p];
        }
        __syncwarp();

        // ---- 2. issue next row's loads now; they fly during the scan below
        if (next < NROWS)
            load_row(R, (long)next * S_STRIDE, seg, lane, Q, eQ, tQ, r, tp, bp);

        // ---- 3. contiguous read-back: lane owns cols seg + 4*lane .. +3
        const float4 a4 = reinterpret_cast<const float4*>(sA [w])[lane];
        const float4 b4 = reinterpret_cast<const float4*>(sB [w])[lane];
        const float4 q4 = reinterpret_cast<const float4*>(sQv[w])[lane];
        Aff loc[4] = { {a4.x, b4.x}, {a4.y, b4.y}, {a4.z, b4.z}, {a4.w, b4.w} };
        const float qv[4] = { q4.x, q4.y, q4.z, q4.w };

        // serial suffix composition within thread
        Aff suf[4];
        suf[3] = loc[3];
#pragma unroll
        for (int k = 2; k >= 0; k--) suf[k] = comp(loc[k], suf[k + 1]);

        // single warp-level inclusive suffix scan of thread aggregates
        Aff v = suf[0];
#pragma unroll
        for (int off = 1; off < 32; off <<= 1) {
            const float oa = __shfl_down_sync(0xffffffffu, v.a, off);
            const float ob = __shfl_down_sync(0xffffffffu, v.b, off);
            if (lane + off < 32) { Aff g; g.a = oa; g.b = ob; v = comp(v, g); }
        }

        // in-warp EXCLUSIVE suffix (threads lane+1..31)
        const float ea = __shfl_down_sync(0xffffffffu, v.a, 1);
        const float eb = __shfl_down_sync(0xffffffffu, v.b, 1);
        Aff inwexcl;
        if (lane == 31) { inwexcl.a = 0.0f; inwexcl.b = 1.0f; }
        else            { inwexcl.a = ea;   inwexcl.b = eb;   }

        // ---- 4. cross-warp: publish totals (double-buffered), ONE barrier,
        //         then redundant per-thread composition of later warps
        if (lane == 0) { swA[buf][w] = v.a; swB[buf][w] = v.b; }
        __syncthreads();
        Aff W; W.a = 0.0f; W.b = 1.0f;
        for (int ww = 7; ww > w; ww--) {
            Aff tot; tot.a = swA[buf][ww]; tot.b = swB[buf][ww];
            W = comp(tot, W);
        }
        const Aff S = comp(inwexcl, W);

        // ---- 5. epilogue: apply composed maps, accumulate squared error
        float fsum = 0.0f;
#pragma unroll
        for (int k = 0; k < 4; k++) {
            const Aff m = comp(suf[k], S);
            const float y = fmaf(m.b, init, m.a);
            const float d = qv[k] - y;
            fsum = fmaf(d, d, fsum);
        }
        acc += (double)fsum;

        buf ^= 1;
        row = next;
    }

    // ---- final: block-reduce per-thread doubles, one arrival per CTA
#pragma unroll
    for (int off = 16; off > 0; off >>= 1)
        acc += __shfl_down_sync(0xffffffffu, acc, off);
    if (lane == 0) ssum[w] = acc;
    __syncthreads();

    if (t == 0) {
        double x = 0.0;
#pragma unroll
        for (int i = 0; i < 8; i++) x += ssum[i];
        __stcg(&g_part[bid], x);
        __threadfence();
        const unsigned old = atomicInc(&g_cnt, GRID - 1);  // wraps after GRID arrivals
        s_last = (old == GRID - 1);
    }
    __syncthreads();

    // ---- very last CTA reduces all partials and writes output
    if (s_last) {
        double x = 0.0;
        for (int i = t; i < GRID; i += NTHREADS)
            x += __ldcg(&g_part[i]);
#pragma unroll
        for (int off = 16; off > 0; off >>= 1)
            x += __shfl_down_sync(0xffffffffu, x, off);
        __shared__ double fs2[8];
        if (lane == 0) fs2[w] = x;
        __syncthreads();
        if (t == 0) {
            double tot = 0.0;
#pragma unroll
            for (int i = 0; i < 8; i++) tot += fs2[i];
            out[0] = (float)(tot / (double)((long long)NROWS * T_LEN));
        }
    }
}

extern "C" void kernel_launch(void* const* d_in, const int* in_sizes, int n_in,
                              void* d_out, int out_size)
{
    const float* Q   = (const float*)d_in[0];
    const float* eQ  = (const float*)d_in[1];
    const float* tQ  = (const float*)d_in[2];
    const float* r   = (const float*)d_in[3];
    const float* tp  = (const float*)d_in[4];
    const float* bp  = (const float*)d_in[5];
    float* out = (float*)d_out;

    retrace_kernel<<<GRID, NTHREADS>>>(Q, eQ, tQ, r, tp, bp, out);
}